// round 12
// baseline (speedup 1.0000x reference)
#include <cuda_runtime.h>
#include <cstdint>

#define LDA 132
#define THREADS 512
#define ROWS 64           // CTA tile rows: 2 groups x 32

// rows: At(64:x) | Hs(64) | Wt(128: Wf/Uf/U-pong) | Pt(128: child bufs / W-ping)
#define SMEM_FLOATS (384*LDA)
#define SMEM_BYTES  (SMEM_FLOATS*4)

__device__ float wbuf[8][128*LDA];   // Wf,Uf,Wu,Uu,Wi,Ui,Wo,Uo : [n][k], tf32-rounded

__device__ __forceinline__ float tf32r(float v){
    uint32_t u; asm("cvt.rna.tf32.f32 %0, %1;" : "=r"(u) : "f"(v));
    return __uint_as_float(u);
}
__device__ __forceinline__ float sigf(float v){
    float t = __expf(-v);
    return __fdividef(1.0f, 1.0f + t);
}
__device__ __forceinline__ float tanhfast(float v){
    v = fminf(fmaxf(v, -15.0f), 15.0f);
    float t = __expf(-2.0f*v);
    return __fdividef(1.0f - t, 1.0f + t);
}

__device__ __forceinline__ void cpa16(uint32_t s, const float* g){
    asm volatile("cp.async.cg.shared.global [%0], [%1], 16;\n" :: "r"(s), "l"(g));
}
#define CP_COMMIT() asm volatile("cp.async.commit_group;\n" ::: "memory")
#define CP_WAIT(n)  asm volatile("cp.async.wait_group %0;\n" :: "n"(n) : "memory")
#define GBAR(id)    asm volatile("bar.sync %0, 256;\n" :: "r"(id) : "memory")

// CTA-wide copy of R x 128 tile (512 threads)
template<int R>
__device__ __forceinline__ void cpa_cta(float* dst, const float* __restrict__ src,
                                        int rs, int tid){
    uint32_t base = (uint32_t)__cvta_generic_to_shared(dst);
    #pragma unroll
    for (int i=0;i<R*32/THREADS;i++){
        int e = tid + i*THREADS;
        int row = e >> 5;
        int c4  = (e & 31) * 4;
        cpa16(base + (uint32_t)(row*LDA + c4)*4u, src + (size_t)row*rs + c4);
    }
}
// group copy of 32 x 128 tile (256 threads of one group)
__device__ __forceinline__ void cpa_grp(float* dst, const float* __restrict__ src,
                                        int rs, int tid2){
    uint32_t base = (uint32_t)__cvta_generic_to_shared(dst);
    #pragma unroll
    for (int i=0;i<4;i++){
        int e = tid2 + i*256;
        int row = e >> 5;
        int c4  = (e & 31) * 4;
        cpa16(base + (uint32_t)(row*LDA + c4)*4u, src + (size_t)row*rs + c4);
    }
}

__device__ __forceinline__ void mma8(float* c, const uint32_t* a, const uint32_t* b){
    asm volatile(
      "mma.sync.aligned.m16n8k8.row.col.f32.tf32.tf32.f32 "
      "{%0,%1,%2,%3},{%4,%5,%6,%7},{%8,%9},{%0,%1,%2,%3};\n"
      : "+f"(c[0]), "+f"(c[1]), "+f"(c[2]), "+f"(c[3])
      : "r"(a[0]), "r"(a[1]), "r"(a[2]), "r"(a[3]),
        "r"(b[0]), "r"(b[1]));
}
__device__ __forceinline__ void ldsm4(uint32_t* d, uint32_t saddr){
    asm volatile("ldmatrix.sync.aligned.m8n8.x4.shared.b16 {%0,%1,%2,%3}, [%4];\n"
      : "=r"(d[0]),"=r"(d[1]),"=r"(d[2]),"=r"(d[3]) : "r"(saddr));
}

// 16x128x128 tf32 GEMM slice: one warp computes 16 rows x 32 cols of a
// group-level 32x128 gemm. As = warp's 16-row slab base; Bs = weights [n][k].
__device__ __forceinline__ void gemm16(float (&acc)[4][4],
                                       const float* __restrict__ As,
                                       const float* __restrict__ Bs,
                                       int lane, int wn)
{
    uint32_t abase = (uint32_t)__cvta_generic_to_shared(As);
    uint32_t bbase = (uint32_t)__cvta_generic_to_shared(Bs);
    int aRow = (lane&7) + ((lane>>3)&1)*8;
    int aCol = ((lane>>4)&1)*4;
    uint32_t aoff = abase + (uint32_t)(aRow*LDA + aCol)*4u;
    int bRow = wn*32 + (lane&7) + ((lane>>4)&1)*8;
    int bCol = ((lane>>3)&1)*4;
    uint32_t boff = bbase + (uint32_t)(bRow*LDA + bCol)*4u;

    #pragma unroll
    for (int k8=0;k8<16;k8++){
        uint32_t a[4], b[2][4];
        ldsm4(a,    aoff + k8*32u);
        ldsm4(b[0], boff + k8*32u);                 // cols wn*32+0..15
        ldsm4(b[1], boff + 16u*LDA*4u + k8*32u);    // cols wn*32+16..31
        mma8(acc[0], a, &b[0][0]);
        mma8(acc[1], a, &b[0][2]);
        mma8(acc[2], a, &b[1][0]);
        mma8(acc[3], a, &b[1][2]);
    }
}

#define ZERO_ACC(A) { _Pragma("unroll") for(int _n=0;_n<4;_n++) _Pragma("unroll") for(int _e=0;_e<4;_e++) (A)[_n][_e]=0.0f; }

// ---- prep: transpose + tf32-round all 8 weight matrices ----------------
__global__ void prep_weights(const float* __restrict__ Wf, const float* __restrict__ Uf,
                             const float* __restrict__ Wu, const float* __restrict__ Uu,
                             const float* __restrict__ Wi, const float* __restrict__ Ui,
                             const float* __restrict__ Wo, const float* __restrict__ Uo)
{
    const float* srcs[8] = {Wf,Uf,Wu,Uu,Wi,Ui,Wo,Uo};
    const float* s = srcs[blockIdx.x];
    float* d = wbuf[blockIdx.x];
    for (int i = threadIdx.x; i < 128*128; i += blockDim.x){
        int n = i >> 7, k = i & 127;
        d[n*LDA + k] = tf32r(s[k*128 + n]);
    }
}

__global__ void __launch_bounds__(THREADS, 1)
treelstm_kernel(const float* __restrict__ x,
                const float* __restrict__ child_h,
                const float* __restrict__ child_c,
                const float* __restrict__ bi, const float* __restrict__ bo,
                const float* __restrict__ bu, const float* __restrict__ bf,
                float* __restrict__ out, int N)
{
    extern __shared__ float smem[];
    float* At = smem;                  // 64 rows: x (tf32), resident
    float* Hs = smem +  64*LDA;        // 64 rows: h_sum staging (gate phase)
    float* Wt = smem + 128*LDA;        // 128 rows: Wf / Uf / U-gate pong
    float* Pt = smem + 256*LDA;        // 128 rows: child bufs / W-gate ping

    const int tid  = threadIdx.x;
    const int tid2 = tid & 255;
    const int lane = tid & 31;
    const int g    = lane >> 2;
    const int r    = lane & 3;
    const int wid  = tid >> 5;
    const int gi   = wid >> 3;          // group 0/1
    const int wl   = wid & 7;
    const int wm   = wl & 1;            // 16-row half within group slab
    const int wn   = wl >> 1;           // 32-col group (0..3)
    const int m0   = blockIdx.x * ROWS;
    const int bid  = gi + 1;            // named barrier id

    float* gbuf0 = Pt + (gi*64     )*LDA;   // group's child ping
    float* gbuf1 = Pt + (gi*64 + 32)*LDA;   // group's child pong

    const int Rr  = wm*16 + g;              // owned rows in slab: Rr, Rr+8
    const int Rg  = m0 + gi*32 + Rr;        // global row
    const float* xslab  = At + (gi*32 + wm*16)*LDA;
    const float* hsslab = Hs + (gi*32 + wm*16)*LDA;
    const size_t chbase = ((size_t)(m0 + gi*32))*8;   // child_h/child_c node base

    float acc [4][4];
    float cacc[4][4];
    float xfv [4][4];   // xf during children, u during gates
    float hs  [4][4];

    #pragma unroll
    for (int nt=0;nt<4;nt++)
      #pragma unroll
      for (int e=0;e<4;e++){ cacc[nt][e]=0.f; hs[nt][e]=0.f; }

    // ---- prologue: x + Wf (CTA), ch0 (group) ---------------------------
    cpa_cta<64 >(At, x + (size_t)m0*128, 128, tid);
    cpa_cta<128>(Wt, wbuf[0], LDA, tid);
    CP_COMMIT();                                       // x + Wf
    cpa_grp(gbuf0, child_h + (chbase + 0)*128, 8*128, tid2);
    CP_COMMIT();                                       // ch0

    CP_WAIT(1); __syncthreads();                       // x + Wf visible
    // round x in place (CTA-wide, own elements)
    #pragma unroll
    for (int i=0;i<4;i++){
        int e = tid + i*THREADS;
        int row = e>>5, c4=(e&31)*4;
        float4* p = reinterpret_cast<float4*>(At + row*LDA + c4);
        float4 v = *p;
        v.x=tf32r(v.x); v.y=tf32r(v.y); v.z=tf32r(v.z); v.w=tf32r(v.w);
        *p = v;
    }
    __syncthreads();

    // ---- phase 1: xf = x @ Wf + bf -------------------------------------
    ZERO_ACC(acc);
    gemm16(acc, xslab, Wt, lane, wn);
    __syncthreads();                                   // Wf done by both groups
    cpa_cta<128>(Wt, wbuf[1], LDA, tid); CP_COMMIT();  // Uf
    cpa_grp(gbuf1, child_h + (chbase + 1)*128, 8*128, tid2);
    CP_COMMIT();                                       // ch1

    #pragma unroll
    for (int nt=0;nt<4;nt++){
        int C0 = wn*32 + nt*8 + 2*r;
        float2 bv = *reinterpret_cast<const float2*>(bf + C0);
        xfv[nt][0] = acc[nt][0] + bv.x;
        xfv[nt][1] = acc[nt][1] + bv.y;
        xfv[nt][2] = acc[nt][2] + bv.x;
        xfv[nt][3] = acc[nt][3] + bv.y;
    }

    // ---- phase 2: children (group-independent, Uf resident) ------------
    for (int k=0;k<8;k++){
        float* buf = (k&1) ? gbuf1 : gbuf0;
        if (k<7) { CP_WAIT(1); } else { CP_WAIT(0); }  // ch_k (+Uf at k=0)
        if (k==0) { __syncthreads(); }                 // Uf: CTA-wide visibility
        else      { GBAR(bid); }                       // ch_k visible to group

        // hs += own slice of raw child tile
        #pragma unroll
        for (int nt=0;nt<4;nt++){
            int C0 = wn*32 + nt*8 + 2*r;
            float2 v0 = *reinterpret_cast<const float2*>(buf +  Rr   *LDA + C0);
            float2 v1 = *reinterpret_cast<const float2*>(buf + (Rr+8)*LDA + C0);
            hs[nt][0] += v0.x; hs[nt][1] += v0.y;
            hs[nt][2] += v1.x; hs[nt][3] += v1.y;
        }

        ZERO_ACC(acc);
        gemm16(acc, buf + wm*16*LDA, Wt, lane, wn);    // ch_k @ Uf (HW tf32-truncates A)

        #pragma unroll
        for (int nt=0;nt<4;nt++){
            int C0 = wn*32 + nt*8 + 2*r;
            float2 c0 = __ldg(reinterpret_cast<const float2*>(child_c + ((size_t)Rg    *8 + k)*128 + C0));
            float2 c1 = __ldg(reinterpret_cast<const float2*>(child_c + ((size_t)(Rg+8)*8 + k)*128 + C0));
            cacc[nt][0] += sigf(xfv[nt][0] + acc[nt][0]) * c0.x;
            cacc[nt][1] += sigf(xfv[nt][1] + acc[nt][1]) * c0.y;
            cacc[nt][2] += sigf(xfv[nt][2] + acc[nt][2]) * c1.x;
            cacc[nt][3] += sigf(xfv[nt][3] + acc[nt][3]) * c1.y;
        }

        GBAR(bid);                                     // group done reading buf
        if (k+2 < 8){
            cpa_grp(buf, child_h + (chbase + (k+2))*128, 8*128, tid2);
            CP_COMMIT();
        }
    }

    // ---- gate prologue: hs -> Hs (tf32), weight ping-pong ---------------
    #pragma unroll
    for (int nt=0;nt<4;nt++){
        int C0 = wn*32 + nt*8 + 2*r;
        float* h0 = Hs + (gi*32 + Rr)*LDA + C0;
        *reinterpret_cast<float2*>(h0) =
            make_float2(tf32r(hs[nt][0]), tf32r(hs[nt][1]));
        *reinterpret_cast<float2*>(h0 + 8*LDA) =
            make_float2(tf32r(hs[nt][2]), tf32r(hs[nt][3]));
    }
    __syncthreads();                                   // children done; Pt free
    cpa_cta<128>(Pt, wbuf[2], LDA, tid); CP_COMMIT();  // Wu (ping)
    cpa_cta<128>(Wt, wbuf[3], LDA, tid); CP_COMMIT();  // Uu (pong)

    const float* bs[3] = {bu, bi, bo};

    // ---- phase 3: gates u, i, o -----------------------------------------
    for (int gate=0; gate<3; gate++){
        CP_WAIT(1); __syncthreads();                   // W_gate visible CTA-wide
        ZERO_ACC(acc);
        gemm16(acc, xslab, Pt, lane, wn);              // x @ W_g
        __syncthreads();                               // ping free
        if (gate<2){ cpa_cta<128>(Pt, wbuf[4 + 2*gate], LDA, tid); CP_COMMIT(); }

        if (gate<2) { CP_WAIT(1); } else { CP_WAIT(0); }
        __syncthreads();                               // U_gate visible
        gemm16(acc, hsslab, Wt, lane, wn);             // + hs @ U_g
        __syncthreads();                               // pong free
        if (gate<2){ cpa_cta<128>(Wt, wbuf[5 + 2*gate], LDA, tid); CP_COMMIT(); }

        const float* bp = bs[gate];
        #pragma unroll
        for (int nt=0;nt<4;nt++){
            int C0 = wn*32 + nt*8 + 2*r;
            float2 bv = *reinterpret_cast<const float2*>(bp + C0);
            float p0 = acc[nt][0] + bv.x;
            float p1 = acc[nt][1] + bv.y;
            float p2 = acc[nt][2] + bv.x;
            float p3 = acc[nt][3] + bv.y;
            if (gate == 0){                            // u = tanh(.)
                xfv[nt][0] = tanhfast(p0);
                xfv[nt][1] = tanhfast(p1);
                xfv[nt][2] = tanhfast(p2);
                xfv[nt][3] = tanhfast(p3);
            } else if (gate == 1){                     // c += sig(i)*u
                cacc[nt][0] += sigf(p0) * xfv[nt][0];
                cacc[nt][1] += sigf(p1) * xfv[nt][1];
                cacc[nt][2] += sigf(p2) * xfv[nt][2];
                cacc[nt][3] += sigf(p3) * xfv[nt][3];
            } else {                                   // o: write h, c
                float c0 = cacc[nt][0], c1 = cacc[nt][1];
                float c2 = cacc[nt][2], c3 = cacc[nt][3];
                float h0 = sigf(p0) * tanhfast(c0);
                float h1 = sigf(p1) * tanhfast(c1);
                float h2 = sigf(p2) * tanhfast(c2);
                float h3 = sigf(p3) * tanhfast(c3);
                float* outh = out;
                float* outc = out + (size_t)N*128;
                *reinterpret_cast<float2*>(outh + (size_t) Rg   *128 + C0) = make_float2(h0,h1);
                *reinterpret_cast<float2*>(outh + (size_t)(Rg+8)*128 + C0) = make_float2(h2,h3);
                *reinterpret_cast<float2*>(outc + (size_t) Rg   *128 + C0) = make_float2(c0,c1);
                *reinterpret_cast<float2*>(outc + (size_t)(Rg+8)*128 + C0) = make_float2(c2,c3);
            }
        }
    }
}

extern "C" void kernel_launch(void* const* d_in, const int* in_sizes, int n_in,
                              void* d_out, int out_size)
{
    const float* x       = (const float*)d_in[0];
    const float* child_h = (const float*)d_in[1];
    const float* child_c = (const float*)d_in[2];
    const float* Wi = (const float*)d_in[3];
    const float* bi = (const float*)d_in[4];
    const float* Ui = (const float*)d_in[5];
    const float* Wo = (const float*)d_in[6];
    const float* bo = (const float*)d_in[7];
    const float* Uo = (const float*)d_in[8];
    const float* Wu = (const float*)d_in[9];
    const float* bu = (const float*)d_in[10];
    const float* Uu = (const float*)d_in[11];
    const float* Wf = (const float*)d_in[12];
    const float* bf = (const float*)d_in[13];
    const float* Uf = (const float*)d_in[14];
    float* out = (float*)d_out;

    int N = in_sizes[0] / 128;
    int blocks = N / ROWS;

    prep_weights<<<8, 256>>>(Wf, Uf, Wu, Uu, Wi, Ui, Wo, Uo);

    cudaFuncSetAttribute(treelstm_kernel,
                         cudaFuncAttributeMaxDynamicSharedMemorySize, SMEM_BYTES);
    treelstm_kernel<<<blocks, THREADS, SMEM_BYTES>>>(
        x, child_h, child_c, bi, bo, bu, bf, out, N);
}